// round 8
// baseline (speedup 1.0000x reference)
#include <cuda_runtime.h>

// STRNNCell: out[b,h] = sigmoid( sum_c mask[b,c] * (x[b,c] @ tw[time[b,c]]) @ dw[dist[b,c]]
//                               + (h[b] @ hidden_weights) )
// B=256, C=50, INPUT=128, INTER=64, HIDDEN=128, slots=11.
// R7: latency-bound (issue 19.7%, L2 6.5%). float4 loads + deep unroll for MLP.

namespace {
constexpr int Bv   = 256;
constexpr int Cv   = 50;
constexpr int INv  = 128;
constexpr int ITv  = 64;
constexpr int HIDv = 128;
constexpr int NSv  = 11;
constexpr int GSZ  = 4;
}

__global__ __launch_bounds__(256, 2)
void strnn_kernel(const float* __restrict__ x,            // (B,C,IN)
                  const int*   __restrict__ tctx,         // (B,C)
                  const int*   __restrict__ dctx,         // (B,C)
                  const unsigned char* __restrict__ mraw, // (B,C) bool OR int32
                  const float* __restrict__ hin,          // (B,HID)
                  const float* __restrict__ tw,           // (NS,IN,IT)
                  const float* __restrict__ dw,           // (NS,IT,HID)
                  const float* __restrict__ hw,           // (HID,HID)
                  float* __restrict__ out)                // (B,HID)
{
    __shared__ __align__(16) float xs[Cv * INv];      // 25.6 KB (reused as red buf in phase 4)
    __shared__ __align__(16) float ts[Cv * ITv];      // 12.8 KB
    __shared__ __align__(16) float U [NSv * ITv];     // 2.8 KB
    __shared__ __align__(16) float hs[HIDv];
    __shared__ int tlist[NSv][Cv];
    __shared__ int tcnt[NSv];
    __shared__ int dcs[Cv];
    __shared__ int mk[Cv];
    __shared__ int gslot[24], gbase[24], gn[24];
    __shared__ int ngroups;
    __shared__ unsigned char dused[NSv];

    const int tid = threadIdx.x;
    const int b   = blockIdx.x;

    // ---- mask dtype detection (bool bytes vs int32) ----
    unsigned int wv = ((const unsigned int*)mraw)[tid & 31];
    const int mask_is_i32 = !__syncthreads_or((int)(wv > 1u));

    // ---- init + stage x, h ----
    if (tid < NSv) { tcnt[tid] = 0; dused[tid] = 0; }
    if (tid == 0) ngroups = 0;
    {
        const float4* __restrict__ xg4 = (const float4*)(x + b * Cv * INv);
        float4* xs4 = (float4*)xs;
        for (int i = tid; i < Cv * INv / 4; i += 256) xs4[i] = xg4[i];
    }
    if (tid < HIDv) hs[tid] = hin[b * HIDv + tid];
    __syncthreads();

    // ---- build per-time-slot lists of masked contexts ----
    if (tid < Cv) {
        const int c = tid;
        const int m = mask_is_i32 ? (((const int*)mraw)[b * Cv + c] != 0)
                                  : (mraw[b * Cv + c] != 0);
        mk[c] = m;
        const int d_ = dctx[b * Cv + c];
        dcs[c] = d_;
        if (m) {
            const int s = tctx[b * Cv + c];
            const int p = atomicAdd(&tcnt[s], 1);
            tlist[s][p] = c;
            dused[d_] = 1;
        }
    }
    __syncthreads();

    if (tid == 0) {
        int ng = 0;
        for (int s = 0; s < NSv; s++)
            for (int off = 0; off < tcnt[s]; off += GSZ) {
                gslot[ng] = s;
                gbase[ng] = off;
                gn[ng]    = min(GSZ, tcnt[s] - off);
                ng++;
            }
        ngroups = ng;   // <= 23
    }
    __syncthreads();

    // ---- phase 2: t[c] = x[b,c] @ tw[s] ----
    // float4 weight loads: lane = (rowpar<<4) | c4. Warp covers rows (2i, 2i+1),
    // 512B contiguous per vec-iter. unroll 8 -> MLP ~8 vs L2 latency.
    {
        const int warp   = tid >> 5, lane = tid & 31;
        const int rowpar = lane >> 4;          // 0/1: odd/even row
        const int c4     = lane & 15;          // float4 col group (4 cols)
        const int ng = ngroups;
        for (int g = warp; g < ng; g += 8) {
            const int s = gslot[g], base = gbase[g], n = gn[g];
            const float4* __restrict__ w4 = (const float4*)(tw + s * INv * ITv); // [128][16]
            int cc[GSZ];
            #pragma unroll
            for (int k = 0; k < GSZ; k++) cc[k] = tlist[s][base + (k < n ? k : 0)];
            float4 a[GSZ];
            #pragma unroll
            for (int k = 0; k < GSZ; k++) a[k] = make_float4(0.f, 0.f, 0.f, 0.f);
            #pragma unroll 8
            for (int ii = 0; ii < INv / 2; ii++) {
                const int i = ii * 2 + rowpar;
                const float4 w = w4[i * 16 + c4];
                #pragma unroll
                for (int k = 0; k < GSZ; k++) {
                    const float xv = xs[cc[k] * INv + i];
                    a[k].x = fmaf(xv, w.x, a[k].x);
                    a[k].y = fmaf(xv, w.y, a[k].y);
                    a[k].z = fmaf(xv, w.z, a[k].z);
                    a[k].w = fmaf(xv, w.w, a[k].w);
                }
            }
            // combine the two row parities (lanes L and L^16 hold complementary rows)
            #pragma unroll
            for (int k = 0; k < GSZ; k++) {
                a[k].x += __shfl_xor_sync(0xffffffffu, a[k].x, 16);
                a[k].y += __shfl_xor_sync(0xffffffffu, a[k].y, 16);
                a[k].z += __shfl_xor_sync(0xffffffffu, a[k].z, 16);
                a[k].w += __shfl_xor_sync(0xffffffffu, a[k].w, 16);
            }
            if (lane < 16) {
                #pragma unroll
                for (int k = 0; k < GSZ; k++)
                    if (k < n) ((float4*)ts)[cc[k] * (ITv / 4) + c4] = a[k];
            }
        }
    }
    __syncthreads();

    // ---- phase 3: U[s] = sum over masked c with dist==s of t[c] ----
    {
        const int j = tid & 63, sq = tid >> 6;
        for (int s = sq; s < NSv; s += 4) {
            float u = 0.f;
            for (int c = 0; c < Cv; c++)
                if (mk[c] && dcs[c] == s) u += ts[c * ITv + j];
            U[s * ITv + j] = u;
        }
    }
    __syncthreads();

    // ---- phase 4: xc = sum_s U[s] @ dw[s]  + h @ hw ----
    // 8 squads x 32 threads; each thread owns 4 output cols (float4).
    float* redf = xs;                 // xs dead after phase 2 -> reuse as 8x128 partials
    {
        const int c4 = tid & 31;      // cols c4*4 .. c4*4+3
        const int sq = tid >> 5;      // 0..7
        float4 acc = make_float4(0.f, 0.f, 0.f, 0.f);
        for (int s = sq; s < NSv; s += 8) {
            if (!dused[s]) continue;
            const float4* __restrict__ w4 = (const float4*)(dw + s * ITv * HIDv); // [64][32]
            #pragma unroll 8
            for (int j = 0; j < ITv; j++) {
                const float uj = U[s * ITv + j];
                const float4 w = w4[j * 32 + c4];
                acc.x = fmaf(uj, w.x, acc.x);
                acc.y = fmaf(uj, w.y, acc.y);
                acc.z = fmaf(uj, w.z, acc.z);
                acc.w = fmaf(uj, w.w, acc.w);
            }
        }
        const float4* __restrict__ hw4 = (const float4*)hw;  // [128][32]
        #pragma unroll 8
        for (int k = sq * 16; k < sq * 16 + 16; k++) {
            const float hv = hs[k];
            const float4 w = hw4[k * 32 + c4];
            acc.x = fmaf(hv, w.x, acc.x);
            acc.y = fmaf(hv, w.y, acc.y);
            acc.z = fmaf(hv, w.z, acc.z);
            acc.w = fmaf(hv, w.w, acc.w);
        }
        ((float4*)redf)[sq * 32 + c4] = acc;  // partial at float offset sq*128 + c4*4
    }
    __syncthreads();

    // ---- final reduce (fixed order over 8 squads) + sigmoid ----
    if (tid < HIDv) {
        float z = 0.f;
        #pragma unroll
        for (int q = 0; q < 8; q++) z += redf[q * HIDv + tid];
        out[b * HIDv + tid] = 1.f / (1.f + expf(-z));
    }
}

extern "C" void kernel_launch(void* const* d_in, const int* in_sizes, int n_in,
                              void* d_out, int out_size) {
    (void)in_sizes; (void)n_in; (void)out_size;
    strnn_kernel<<<Bv, 256>>>(
        (const float*)d_in[0],
        (const int*)d_in[1],
        (const int*)d_in[2],
        (const unsigned char*)d_in[3],
        (const float*)d_in[4],
        (const float*)d_in[5],
        (const float*)d_in[6],
        (const float*)d_in[7],
        (float*)d_out);
}